// round 1
// baseline (speedup 1.0000x reference)
#include <cuda_runtime.h>
#include <cstddef>

// Problem constants
#define T_TOKENS 131072      // 8*128*128
#define C_DIM    320
#define QKV_N    960
#define MLP_N    1280
#define N_WINDOWS 2048       // 8 * 16 * 16
#define HEADS    32
#define DHEAD    10

// ---------------- scratch (device globals; no allocation allowed) -------------
__device__ float g_xn [ (size_t)T_TOKENS * C_DIM  ];   // normalized x (reused for xn2)
__device__ float g_qkv[ (size_t)T_TOKENS * QKV_N  ];   // qkv projections
__device__ float g_o  [ (size_t)T_TOKENS * C_DIM  ];   // attention output (pre-proj)
__device__ float g_xa [ (size_t)T_TOKENS * C_DIM  ];   // x + attn branch
__device__ float g_h  [ (size_t)T_TOKENS * MLP_N  ];   // mlp hidden

// ---------------- l2 normalize along C=320, one warp per token ----------------
__global__ __launch_bounds__(256) void l2norm_kernel(const float* __restrict__ in,
                                                     float* __restrict__ out) {
    int row  = blockIdx.x * 8 + (threadIdx.x >> 5);
    int lane = threadIdx.x & 31;
    const float* p = in + (size_t)row * C_DIM;
    float v[10];
    float s = 0.f;
#pragma unroll
    for (int i = 0; i < 10; i++) { v[i] = p[lane + 32 * i]; s += v[i] * v[i]; }
#pragma unroll
    for (int sh = 16; sh; sh >>= 1) s += __shfl_xor_sync(0xffffffffu, s, sh);
    float n = sqrtf(s);
    n = fmaxf(n, 1e-12f);
    float inv = 1.0f / n;
    float* q = out + (size_t)row * C_DIM;
#pragma unroll
    for (int i = 0; i < 10; i++) q[lane + 32 * i] = v[i] * inv;
}

// ---------------- SGEMM: C = epilogue(A[MxK] @ B[KxN]) ------------------------
// BM=128, BN=64, BK=16, 256 threads, 8x4 micro-tile per thread.
// All shapes used here divide the tiles exactly (no bounds checks).
// EPI: 0 = +bias (qkv)
//      1 = +bias +res (proj, res stride N=320)
//      2 = relu (mlp1, no bias)
//      3 = res + relu(acc+bias)*gamma (mlp2 / final output)
#define BM 128
#define BN 64
#define BK 16

template <int EPI>
__global__ __launch_bounds__(256) void sgemm_kernel(
    const float* __restrict__ A, const float* __restrict__ Bw,
    const float* __restrict__ bias, const float* __restrict__ res,
    const float* __restrict__ gamma, float* __restrict__ Cout,
    int M, int N, int K)
{
    __shared__ float As[BK][BM + 4];   // +4 pad: row stride 132 floats (16B aligned)
    __shared__ float Bs[BK][BN + 4];   // +4 pad: row stride 68 floats (16B aligned)

    const int bm = blockIdx.y * BM;
    const int bn = blockIdx.x * BN;
    const int tid = threadIdx.x;
    const int tx = tid & 15;           // 16 col-groups * 4 cols
    const int ty = tid >> 4;           // 16 row-groups * 8 rows

    float acc[8][4];
#pragma unroll
    for (int i = 0; i < 8; i++)
#pragma unroll
        for (int j = 0; j < 4; j++) acc[i][j] = 0.f;

    for (int k0 = 0; k0 < K; k0 += BK) {
        // Load A tile 128x16 (2 float4 per thread), store transposed
#pragma unroll
        for (int u = 0; u < 2; u++) {
            int f = tid + u * 256;
            int r = f >> 2;
            int cs = (f & 3) << 2;
            const float4 v = *reinterpret_cast<const float4*>(
                A + (size_t)(bm + r) * K + k0 + cs);
            As[cs + 0][r] = v.x; As[cs + 1][r] = v.y;
            As[cs + 2][r] = v.z; As[cs + 3][r] = v.w;
        }
        // Load B tile 16x64 (1 float4 per thread)
        {
            int r = tid >> 4;
            int cs = (tid & 15) << 2;
            *reinterpret_cast<float4*>(&Bs[r][cs]) =
                *reinterpret_cast<const float4*>(Bw + (size_t)(k0 + r) * N + bn + cs);
        }
        __syncthreads();

#pragma unroll
        for (int kk = 0; kk < BK; kk++) {
            float4 a0 = *reinterpret_cast<float4*>(&As[kk][ty * 8]);
            float4 a1 = *reinterpret_cast<float4*>(&As[kk][ty * 8 + 4]);
            float4 b  = *reinterpret_cast<float4*>(&Bs[kk][tx * 4]);
            float av[8] = {a0.x, a0.y, a0.z, a0.w, a1.x, a1.y, a1.z, a1.w};
            float bv[4] = {b.x, b.y, b.z, b.w};
#pragma unroll
            for (int i = 0; i < 8; i++)
#pragma unroll
                for (int j = 0; j < 4; j++)
                    acc[i][j] += av[i] * bv[j];
        }
        __syncthreads();
    }

    // Epilogue + vectorized store
    const int nbase = bn + tx * 4;
#pragma unroll
    for (int i = 0; i < 8; i++) {
        const int m = bm + ty * 8 + i;
        float4 o;
        float vv[4];
#pragma unroll
        for (int j = 0; j < 4; j++) {
            const int n = nbase + j;
            float v = acc[i][j];
            if (EPI == 0) {
                v += bias[n];
            } else if (EPI == 1) {
                v += bias[n] + res[(size_t)m * N + n];
            } else if (EPI == 2) {
                v = fmaxf(v, 0.f);
            } else { // EPI == 3
                v = res[(size_t)m * N + n] + fmaxf(v + bias[n], 0.f) * gamma[n];
            }
            vv[j] = v;
        }
        o.x = vv[0]; o.y = vv[1]; o.z = vv[2]; o.w = vv[3];
        *reinterpret_cast<float4*>(Cout + (size_t)m * N + nbase) = o;
    }
}

// ---------------- window attention: one block per window ----------------------
// Reads g_qkv (T x 960, channel = head*30 + {q:0..9, k:10..19, v:20..29}),
// writes g_o (T x 320, channel = head*10 + d). Natural token row layout.
__global__ __launch_bounds__(256) void attn_kernel(const float* __restrict__ qkv,
                                                   float* __restrict__ o) {
    const int w   = blockIdx.x;
    const int b   = w >> 8;            // 256 windows per batch image
    const int rem = w & 255;
    const int wh  = rem >> 4;
    const int ww  = rem & 15;
    const int tid = threadIdx.x;

    __shared__ float qs[64][10];
    __shared__ float ks[64][10];
    __shared__ float vs[64][10];
    __shared__ float sc[64][65];
    __shared__ int   grow[64];

    if (tid < 64) {
        int i = tid >> 3, j = tid & 7;
        grow[tid] = (b * 128 + wh * 8 + i) * 128 + ww * 8 + j;
    }
    __syncthreads();

    const float scale = 0.31622776601683794f;   // 10^-0.5

    for (int h = 0; h < HEADS; h++) {
        // load q,k,v for this head
        for (int idx = tid; idx < 64 * 30; idx += 256) {
            int n = idx / 30, c = idx % 30;
            float v = qkv[(size_t)grow[n] * QKV_N + h * 30 + c];
            if (c < 10)      qs[n][c]      = v;
            else if (c < 20) ks[n][c - 10] = v;
            else             vs[n][c - 20] = v;
        }
        __syncthreads();

        // scores = q @ k^T * scale
        for (int idx = tid; idx < 64 * 64; idx += 256) {
            int r = idx >> 6, cc = idx & 63;
            float s = 0.f;
#pragma unroll
            for (int d = 0; d < 10; d++) s += qs[r][d] * ks[cc][d];
            sc[r][cc] = s * scale;
        }
        __syncthreads();

        // softmax per row (one warp handles 8 rows)
        {
            int lane = tid & 31, warp = tid >> 5;
            for (int r = warp; r < 64; r += 8) {
                float v0 = sc[r][lane], v1 = sc[r][lane + 32];
                float mx = fmaxf(v0, v1);
#pragma unroll
                for (int s = 16; s; s >>= 1) mx = fmaxf(mx, __shfl_xor_sync(0xffffffffu, mx, s));
                float e0 = __expf(v0 - mx), e1 = __expf(v1 - mx);
                float sm = e0 + e1;
#pragma unroll
                for (int s = 16; s; s >>= 1) sm += __shfl_xor_sync(0xffffffffu, sm, s);
                float inv = 1.0f / sm;
                sc[r][lane]      = e0 * inv;
                sc[r][lane + 32] = e1 * inv;
            }
        }
        __syncthreads();

        // o = attn @ v  -> global (channel = h*10 + d)
        for (int idx = tid; idx < 64 * 10; idx += 256) {
            int r = idx / 10, d = idx % 10;
            float s = 0.f;
#pragma unroll 8
            for (int m = 0; m < 64; m++) s += sc[r][m] * vs[m][d];
            o[(size_t)grow[r] * C_DIM + h * DHEAD + d] = s;
        }
        __syncthreads();
    }
}

// ---------------- launch ------------------------------------------------------
extern "C" void kernel_launch(void* const* d_in, const int* in_sizes, int n_in,
                              void* d_out, int out_size) {
    const float* x      = (const float*)d_in[0];
    const float* qkv_w  = (const float*)d_in[1];
    const float* qkv_b  = (const float*)d_in[2];
    const float* proj_w = (const float*)d_in[3];
    const float* proj_b = (const float*)d_in[4];
    const float* gamma  = (const float*)d_in[5];
    const float* w1     = (const float*)d_in[6];
    const float* w2     = (const float*)d_in[7];
    const float* b2     = (const float*)d_in[8];
    float* out = (float*)d_out;

    float *xn, *qkv, *ov, *xa, *hh;
    cudaGetSymbolAddress((void**)&xn,  g_xn);
    cudaGetSymbolAddress((void**)&qkv, g_qkv);
    cudaGetSymbolAddress((void**)&ov,  g_o);
    cudaGetSymbolAddress((void**)&xa,  g_xa);
    cudaGetSymbolAddress((void**)&hh,  g_h);

    const int M = T_TOKENS;
    dim3 blk(256);

    // 1. xn = l2norm(x)
    l2norm_kernel<<<M / 8, blk>>>(x, xn);

    // 2. qkv = xn @ qkv_w + qkv_b
    sgemm_kernel<0><<<dim3(QKV_N / BN, M / BM), blk>>>(
        xn, qkv_w, qkv_b, nullptr, nullptr, qkv, M, QKV_N, C_DIM);

    // 3. windowed multi-head attention -> ov
    attn_kernel<<<N_WINDOWS, blk>>>(qkv, ov);

    // 4. xa = xn + ov @ proj_w + proj_b
    sgemm_kernel<1><<<dim3(C_DIM / BN, M / BM), blk>>>(
        ov, proj_w, proj_b, xn, nullptr, xa, M, C_DIM, C_DIM);

    // 5. xn = l2norm(xa)   (xn2)
    l2norm_kernel<<<M / 8, blk>>>(xa, xn);

    // 6. hh = relu(xn @ w1)
    sgemm_kernel<2><<<dim3(MLP_N / BN, M / BM), blk>>>(
        xn, w1, nullptr, nullptr, nullptr, hh, M, MLP_N, C_DIM);

    // 7. out = xn + relu(hh @ w2 + b2) * gamma
    sgemm_kernel<3><<<dim3(C_DIM / BN, M / BM), blk>>>(
        hh, w2, b2, xn, gamma, out, M, C_DIM, MLP_N);
}

// round 4
// speedup vs baseline: 2.5760x; 2.5760x over previous
#include <cuda_runtime.h>
#include <cuda_bf16.h>
#include <cstdint>
#include <cstddef>

// Problem constants
#define T_TOKENS 131072      // 8*128*128
#define C_DIM    320
#define QKV_N    960
#define MLP_N    1280
#define N_WINDOWS 2048
#define HEADS    32
#define DHEAD    10

// ---------------- scratch (device globals) ------------------------------------
__device__ float          g_xn [ (size_t)T_TOKENS * C_DIM ];
__device__ __nv_bfloat16  g_xnb[ (size_t)T_TOKENS * C_DIM ];
__device__ float          g_qkv[ (size_t)T_TOKENS * QKV_N ];
__device__ float          g_o  [ (size_t)T_TOKENS * C_DIM ];
__device__ float          g_xa [ (size_t)T_TOKENS * C_DIM ];
__device__ __nv_bfloat16  g_h  [ (size_t)T_TOKENS * MLP_N ];
__device__ __nv_bfloat16  g_w1b[ (size_t)C_DIM * MLP_N ];
__device__ __nv_bfloat16  g_w2b[ (size_t)MLP_N * C_DIM ];

// ---------------- asm helpers --------------------------------------------------
#define CP_ASYNC16(dst_u32, src_ptr) \
    asm volatile("cp.async.cg.shared.global [%0], [%1], 16;\n" :: "r"(dst_u32), "l"(src_ptr))
#define CP_COMMIT() asm volatile("cp.async.commit_group;\n" ::)
#define CP_WAIT(n)  asm volatile("cp.async.wait_group %0;\n" :: "n"(n))

__device__ __forceinline__ uint32_t smem_u32(const void* p) {
    return (uint32_t)__cvta_generic_to_shared(p);
}

#define LDSM_X4(r0,r1,r2,r3,addr) \
    asm volatile("ldmatrix.sync.aligned.m8n8.x4.shared.b16 {%0,%1,%2,%3},[%4];\n" \
        : "=r"(r0),"=r"(r1),"=r"(r2),"=r"(r3) : "r"(addr))
#define LDSM_X4T(r0,r1,r2,r3,addr) \
    asm volatile("ldmatrix.sync.aligned.m8n8.x4.trans.shared.b16 {%0,%1,%2,%3},[%4];\n" \
        : "=r"(r0),"=r"(r1),"=r"(r2),"=r"(r3) : "r"(addr))

#define MMA_BF16(c, a, b) \
    asm volatile("mma.sync.aligned.m16n8k16.row.col.f32.bf16.bf16.f32 " \
        "{%0,%1,%2,%3},{%4,%5,%6,%7},{%8,%9},{%0,%1,%2,%3};\n" \
        : "+f"(c[0]),"+f"(c[1]),"+f"(c[2]),"+f"(c[3]) \
        : "r"(a[0]),"r"(a[1]),"r"(a[2]),"r"(a[3]),"r"(b[0]),"r"(b[1]))

#define MMA_TF32(c, a, b) \
    asm volatile("mma.sync.aligned.m16n8k8.row.col.f32.tf32.tf32.f32 " \
        "{%0,%1,%2,%3},{%4,%5,%6,%7},{%8,%9},{%0,%1,%2,%3};\n" \
        : "+f"(c[0]),"+f"(c[1]),"+f"(c[2]),"+f"(c[3]) \
        : "r"(a[0]),"r"(a[1]),"r"(a[2]),"r"(a[3]),"r"(b[0]),"r"(b[1]))

__device__ __forceinline__ uint32_t f2tf32(float x) {
    uint32_t r;
    asm("cvt.rna.tf32.f32 %0, %1;\n" : "=r"(r) : "f"(x));
    return r;
}

// ---------------- l2 normalize along C=320, one warp per token ----------------
template <bool WRITE_BF16>
__global__ __launch_bounds__(256) void l2norm_kernel(const float* __restrict__ in,
                                                     float* __restrict__ out,
                                                     __nv_bfloat16* __restrict__ outb) {
    int row  = blockIdx.x * 8 + (threadIdx.x >> 5);
    int lane = threadIdx.x & 31;
    const float* p = in + (size_t)row * C_DIM;
    float v[10];
    float s = 0.f;
#pragma unroll
    for (int i = 0; i < 10; i++) { v[i] = p[lane + 32 * i]; s += v[i] * v[i]; }
#pragma unroll
    for (int sh = 16; sh; sh >>= 1) s += __shfl_xor_sync(0xffffffffu, s, sh);
    float n = fmaxf(sqrtf(s), 1e-12f);
    float inv = 1.0f / n;
    float* q = out + (size_t)row * C_DIM;
#pragma unroll
    for (int i = 0; i < 10; i++) {
        float o = v[i] * inv;
        q[lane + 32 * i] = o;
        if (WRITE_BF16) outb[(size_t)row * C_DIM + lane + 32 * i] = __float2bfloat16(o);
    }
}

// ---------------- fp32 -> bf16 conversion (weights) ---------------------------
__global__ __launch_bounds__(256) void cvt_bf16_kernel(const float* __restrict__ in,
                                                       __nv_bfloat16* __restrict__ out) {
    int i = (blockIdx.x * 256 + threadIdx.x) * 4;
    float4 v = *reinterpret_cast<const float4*>(in + i);
    __nv_bfloat162 lo = __float22bfloat162_rn(make_float2(v.x, v.y));
    __nv_bfloat162 hi = __float22bfloat162_rn(make_float2(v.z, v.w));
    uint32_t lou, hiu;
    memcpy(&lou, &lo, 4); memcpy(&hiu, &hi, 4);
    uint2 pk = make_uint2(lou, hiu);
    *reinterpret_cast<uint2*>(out + i) = pk;
}

// ---------------- tf32 GEMM: 128x64x16 block, 8 warps (4m x 2n), 32x32 warp ---
// EPI 0: out = acc + bias          (qkv)
// EPI 1: out = acc + bias + res    (proj -> xa)
template <int EPI>
__global__ __launch_bounds__(256) void gemm_tf32(
    const float* __restrict__ A, const float* __restrict__ Bw,
    const float* __restrict__ bias, const float* __restrict__ res,
    float* __restrict__ Cout, int M, int N, int K)
{
    __shared__ float As[2][128][20];   // 128 x 16, pad->20
    __shared__ float Bs[2][16][72];    //  16 x 64, pad->72

    const int tid = threadIdx.x, lane = tid & 31, wid = tid >> 5;
    const int wm = (wid >> 1) * 32, wn = (wid & 1) * 32;
    const int bm = blockIdx.y * 128, bn = blockIdx.x * 64;

    float acc[2][4][4];
#pragma unroll
    for (int i = 0; i < 2; i++)
#pragma unroll
        for (int j = 0; j < 4; j++)
#pragma unroll
            for (int r = 0; r < 4; r++) acc[i][j][r] = 0.f;

    const int ar = tid >> 2, ac = (tid & 3) * 4;            // A: 2 chunks/thread
    const int br = tid >> 4, bc = (tid & 15) * 4;           // B: 1 chunk/thread

    // prologue
    {
        CP_ASYNC16(smem_u32(&As[0][ar][ac]),       A + (size_t)(bm + ar) * K + ac);
        CP_ASYNC16(smem_u32(&As[0][ar + 64][ac]),  A + (size_t)(bm + ar + 64) * K + ac);
        CP_ASYNC16(smem_u32(&Bs[0][br][bc]),       Bw + (size_t)br * N + bn + bc);
        CP_COMMIT();
    }

    const int TT = K / 16;
    for (int t = 0; t < TT; t++) {
        int s = t & 1;
        if (t + 1 < TT) {
            int k0 = (t + 1) * 16;
            CP_ASYNC16(smem_u32(&As[s ^ 1][ar][ac]),      A + (size_t)(bm + ar) * K + k0 + ac);
            CP_ASYNC16(smem_u32(&As[s ^ 1][ar + 64][ac]), A + (size_t)(bm + ar + 64) * K + k0 + ac);
            CP_ASYNC16(smem_u32(&Bs[s ^ 1][br][bc]),      Bw + (size_t)(k0 + br) * N + bn + bc);
            CP_COMMIT();
            CP_WAIT(1);
        } else {
            CP_WAIT(0);
        }
        __syncthreads();

        const int g = lane >> 2, tg = lane & 3;
#pragma unroll
        for (int ks = 0; ks < 2; ks++) {
            uint32_t af[2][4], bf[4][2];
#pragma unroll
            for (int mt = 0; mt < 2; mt++) {
                int r0 = wm + mt * 16 + g;
                af[mt][0] = f2tf32(As[s][r0][ks * 8 + tg]);
                af[mt][1] = f2tf32(As[s][r0 + 8][ks * 8 + tg]);
                af[mt][2] = f2tf32(As[s][r0][ks * 8 + tg + 4]);
                af[mt][3] = f2tf32(As[s][r0 + 8][ks * 8 + tg + 4]);
            }
#pragma unroll
            for (int nt = 0; nt < 4; nt++) {
                int c0 = wn + nt * 8 + g;
                bf[nt][0] = f2tf32(Bs[s][ks * 8 + tg][c0]);
                bf[nt][1] = f2tf32(Bs[s][ks * 8 + tg + 4][c0]);
            }
#pragma unroll
            for (int mt = 0; mt < 2; mt++)
#pragma unroll
                for (int nt = 0; nt < 4; nt++)
                    MMA_TF32(acc[mt][nt], af[mt], bf[nt]);
        }
        __syncthreads();
    }

    // epilogue
    const int g = lane >> 2, tg = lane & 3;
#pragma unroll
    for (int mt = 0; mt < 2; mt++) {
#pragma unroll
        for (int nt = 0; nt < 4; nt++) {
            int r0 = bm + wm + mt * 16 + g;
            int c0 = bn + wn + nt * 8 + tg * 2;
            float b0 = bias[c0], b1 = bias[c0 + 1];
#pragma unroll
            for (int half = 0; half < 2; half++) {
                int r = r0 + half * 8;
                float v0 = acc[mt][nt][half * 2 + 0] + b0;
                float v1 = acc[mt][nt][half * 2 + 1] + b1;
                if (EPI == 1) {
                    float2 rr = *reinterpret_cast<const float2*>(res + (size_t)r * N + c0);
                    v0 += rr.x; v1 += rr.y;
                }
                *reinterpret_cast<float2*>(Cout + (size_t)r * N + c0) = make_float2(v0, v1);
            }
        }
    }
}

// ---------------- bf16 GEMM: 128x64x32 block, 8 warps (4m x 2n), 32x32 warp ---
// EPI 2: out(bf16) = relu(acc)                         (mlp1 -> h)
// EPI 3: out(f32)  = res + relu(acc + bias) * gamma    (mlp2 -> final)
template <int EPI>
__global__ __launch_bounds__(256) void gemm_bf16(
    const __nv_bfloat16* __restrict__ A, const __nv_bfloat16* __restrict__ Bw,
    const float* __restrict__ bias, const float* __restrict__ res,
    const float* __restrict__ gamma, void* __restrict__ Cout,
    int M, int N, int K)
{
    __shared__ __nv_bfloat16 As[2][128][40];   // 128 x 32, pad->40 (80B stride)
    __shared__ __nv_bfloat16 Bs[2][32][72];    //  32 x 64, pad->72 (144B stride)

    const int tid = threadIdx.x, lane = tid & 31, wid = tid >> 5;
    const int wm = (wid >> 1) * 32, wn = (wid & 1) * 32;
    const int bm = blockIdx.y * 128, bn = blockIdx.x * 64;

    float acc[2][4][4];
#pragma unroll
    for (int i = 0; i < 2; i++)
#pragma unroll
        for (int j = 0; j < 4; j++)
#pragma unroll
            for (int r = 0; r < 4; r++) acc[i][j][r] = 0.f;

    const int ar = tid >> 2, ac = (tid & 3) * 8;   // A: 2 chunks/thread (rows ar, ar+64)
    const int br = tid >> 3, bc = (tid & 7) * 8;   // B: 1 chunk/thread

    {
        CP_ASYNC16(smem_u32(&As[0][ar][ac]),      A + (size_t)(bm + ar) * K + ac);
        CP_ASYNC16(smem_u32(&As[0][ar + 64][ac]), A + (size_t)(bm + ar + 64) * K + ac);
        CP_ASYNC16(smem_u32(&Bs[0][br][bc]),      Bw + (size_t)br * N + bn + bc);
        CP_COMMIT();
    }

    const int TT = K / 32;
    for (int t = 0; t < TT; t++) {
        int s = t & 1;
        if (t + 1 < TT) {
            int k0 = (t + 1) * 32;
            CP_ASYNC16(smem_u32(&As[s ^ 1][ar][ac]),      A + (size_t)(bm + ar) * K + k0 + ac);
            CP_ASYNC16(smem_u32(&As[s ^ 1][ar + 64][ac]), A + (size_t)(bm + ar + 64) * K + k0 + ac);
            CP_ASYNC16(smem_u32(&Bs[s ^ 1][br][bc]),      Bw + (size_t)(k0 + br) * N + bn + bc);
            CP_COMMIT();
            CP_WAIT(1);
        } else {
            CP_WAIT(0);
        }
        __syncthreads();

#pragma unroll
        for (int ks = 0; ks < 2; ks++) {
            uint32_t af[2][4], bf[4][2];
#pragma unroll
            for (int mt = 0; mt < 2; mt++) {
                uint32_t addr = smem_u32(&As[s][wm + mt * 16 + (lane & 15)][ks * 16 + (lane >> 4) * 8]);
                LDSM_X4(af[mt][0], af[mt][1], af[mt][2], af[mt][3], addr);
            }
#pragma unroll
            for (int p = 0; p < 2; p++) {
                int row = ks * 16 + ((lane >> 3) & 1) * 8 + (lane & 7);
                int col = wn + p * 16 + (lane >> 4) * 8;
                uint32_t r0, r1, r2, r3;
                uint32_t addr = smem_u32(&Bs[s][row][col]);
                LDSM_X4T(r0, r1, r2, r3, addr);
                bf[p * 2][0] = r0; bf[p * 2][1] = r1;
                bf[p * 2 + 1][0] = r2; bf[p * 2 + 1][1] = r3;
            }
#pragma unroll
            for (int mt = 0; mt < 2; mt++)
#pragma unroll
                for (int nt = 0; nt < 4; nt++)
                    MMA_BF16(acc[mt][nt], af[mt], bf[nt]);
        }
        __syncthreads();
    }

    // epilogue
    const int g = lane >> 2, tg = lane & 3;
#pragma unroll
    for (int mt = 0; mt < 2; mt++) {
#pragma unroll
        for (int nt = 0; nt < 4; nt++) {
            int r0 = bm + wm + mt * 16 + g;
            int c0 = bn + wn + nt * 8 + tg * 2;
#pragma unroll
            for (int half = 0; half < 2; half++) {
                int r = r0 + half * 8;
                float v0 = acc[mt][nt][half * 2 + 0];
                float v1 = acc[mt][nt][half * 2 + 1];
                if (EPI == 2) {
                    v0 = fmaxf(v0, 0.f); v1 = fmaxf(v1, 0.f);
                    __nv_bfloat162 pk = __float22bfloat162_rn(make_float2(v0, v1));
                    uint32_t pku; memcpy(&pku, &pk, 4);
                    *reinterpret_cast<uint32_t*>((__nv_bfloat16*)Cout + (size_t)r * N + c0) = pku;
                } else { // EPI == 3
                    float2 rr = *reinterpret_cast<const float2*>(res + (size_t)r * N + c0);
                    float o0 = rr.x + fmaxf(v0 + bias[c0], 0.f) * gamma[c0];
                    float o1 = rr.y + fmaxf(v1 + bias[c0 + 1], 0.f) * gamma[c0 + 1];
                    *reinterpret_cast<float2*>((float*)Cout + (size_t)r * N + c0) = make_float2(o0, o1);
                }
            }
        }
    }
}

// ---------------- window attention: one block per window ----------------------
__global__ __launch_bounds__(256) void attn_kernel(const float* __restrict__ qkv,
                                                   float* __restrict__ o) {
    const int w   = blockIdx.x;
    const int b   = w >> 8;
    const int rem = w & 255;
    const int wh  = rem >> 4;
    const int ww  = rem & 15;
    const int tid = threadIdx.x;

    __shared__ float qs[64][10];
    __shared__ float ks[64][10];
    __shared__ float vs[64][10];
    __shared__ float sc[64][65];
    __shared__ int   grow[64];

    if (tid < 64) {
        int i = tid >> 3, j = tid & 7;
        grow[tid] = (b * 128 + wh * 8 + i) * 128 + ww * 8 + j;
    }
    __syncthreads();

    const float scale = 0.31622776601683794f;

    for (int h = 0; h < HEADS; h++) {
        for (int idx = tid; idx < 64 * 30; idx += 256) {
            int n = idx / 30, c = idx % 30;
            float v = qkv[(size_t)grow[n] * QKV_N + h * 30 + c];
            if (c < 10)      qs[n][c]      = v;
            else if (c < 20) ks[n][c - 10] = v;
            else             vs[n][c - 20] = v;
        }
        __syncthreads();

        for (int idx = tid; idx < 64 * 64; idx += 256) {
            int r = idx >> 6, cc = idx & 63;
            float s = 0.f;
#pragma unroll
            for (int d = 0; d < 10; d++) s += qs[r][d] * ks[cc][d];
            sc[r][cc] = s * scale;
        }
        __syncthreads();

        {
            int lane = tid & 31, warp = tid >> 5;
            for (int r = warp; r < 64; r += 8) {
                float v0 = sc[r][lane], v1 = sc[r][lane + 32];
                float mx = fmaxf(v0, v1);
#pragma unroll
                for (int s = 16; s; s >>= 1) mx = fmaxf(mx, __shfl_xor_sync(0xffffffffu, mx, s));
                float e0 = __expf(v0 - mx), e1 = __expf(v1 - mx);
                float sm = e0 + e1;
#pragma unroll
                for (int s = 16; s; s >>= 1) sm += __shfl_xor_sync(0xffffffffu, sm, s);
                float inv = 1.0f / sm;
                sc[r][lane]      = e0 * inv;
                sc[r][lane + 32] = e1 * inv;
            }
        }
        __syncthreads();

        for (int idx = tid; idx < 64 * 10; idx += 256) {
            int r = idx / 10, d = idx % 10;
            float s = 0.f;
#pragma unroll 8
            for (int m = 0; m < 64; m++) s += sc[r][m] * vs[m][d];
            o[(size_t)grow[r] * C_DIM + h * DHEAD + d] = s;
        }
        __syncthreads();
    }
}

// ---------------- launch ------------------------------------------------------
extern "C" void kernel_launch(void* const* d_in, const int* in_sizes, int n_in,
                              void* d_out, int out_size) {
    const float* x      = (const float*)d_in[0];
    const float* qkv_w  = (const float*)d_in[1];
    const float* qkv_b  = (const float*)d_in[2];
    const float* proj_w = (const float*)d_in[3];
    const float* proj_b = (const float*)d_in[4];
    const float* gamma  = (const float*)d_in[5];
    const float* w1     = (const float*)d_in[6];
    const float* w2     = (const float*)d_in[7];
    const float* b2     = (const float*)d_in[8];
    float* out = (float*)d_out;

    float *xn, *qkv, *ov, *xa;
    __nv_bfloat16 *xnb, *hh, *w1b, *w2b;
    cudaGetSymbolAddress((void**)&xn,  g_xn);
    cudaGetSymbolAddress((void**)&xnb, g_xnb);
    cudaGetSymbolAddress((void**)&qkv, g_qkv);
    cudaGetSymbolAddress((void**)&ov,  g_o);
    cudaGetSymbolAddress((void**)&xa,  g_xa);
    cudaGetSymbolAddress((void**)&hh,  g_h);
    cudaGetSymbolAddress((void**)&w1b, g_w1b);
    cudaGetSymbolAddress((void**)&w2b, g_w2b);

    const int M = T_TOKENS;
    dim3 blk(256);

    // weight conversions (f32 -> bf16), 409600 elems each
    cvt_bf16_kernel<<<400, blk>>>(w1, w1b);
    cvt_bf16_kernel<<<400, blk>>>(w2, w2b);

    // 1. xn = l2norm(x)
    l2norm_kernel<false><<<M / 8, blk>>>(x, xn, nullptr);

    // 2. qkv = xn @ qkv_w + qkv_b        (tf32)
    gemm_tf32<0><<<dim3(QKV_N / 64, M / 128), blk>>>(xn, qkv_w, qkv_b, nullptr, qkv, M, QKV_N, C_DIM);

    // 3. windowed multi-head attention -> ov
    attn_kernel<<<N_WINDOWS, blk>>>(qkv, ov);

    // 4. xa = xn + ov @ proj_w + proj_b  (tf32)
    gemm_tf32<1><<<dim3(C_DIM / 64, M / 128), blk>>>(ov, proj_w, proj_b, xn, xa, M, C_DIM, C_DIM);

    // 5. xn,xnb = l2norm(xa)
    l2norm_kernel<true><<<M / 8, blk>>>(xa, xn, xnb);

    // 6. h = relu(xnb @ w1b)             (bf16, bf16 out)
    gemm_bf16<2><<<dim3(MLP_N / 64, M / 128), blk>>>(xnb, w1b, nullptr, nullptr, nullptr, hh, M, MLP_N, C_DIM);

    // 7. out = xn + relu(h @ w2b + b2) * gamma   (bf16)
    gemm_bf16<3><<<dim3(C_DIM / 64, M / 128), blk>>>(hh, w2b, b2, xn, gamma, out, M, C_DIM, MLP_N);
}

// round 5
// speedup vs baseline: 3.3965x; 1.3185x over previous
#include <cuda_runtime.h>
#include <cuda_bf16.h>
#include <cstdint>
#include <cstddef>

// Problem constants
#define T_TOKENS 131072      // 8*128*128
#define C_DIM    320
#define QKV_N    960
#define MLP_N    1280
#define HEADS    32
#define DHEAD    10

// ---------------- scratch (device globals) ------------------------------------
__device__ float          g_xn  [ (size_t)T_TOKENS * C_DIM ];
__device__ __nv_bfloat16  g_xnb [ (size_t)T_TOKENS * C_DIM ];
__device__ float          g_qkv [ (size_t)T_TOKENS * QKV_N ];
__device__ float          g_o   [ (size_t)T_TOKENS * C_DIM ];   // tf32-rounded at write
__device__ float          g_xa  [ (size_t)T_TOKENS * C_DIM ];
__device__ __nv_bfloat16  g_h   [ (size_t)T_TOKENS * MLP_N ];
__device__ __nv_bfloat16  g_qwb [ (size_t)C_DIM * QKV_N ];
__device__ float          g_pwt [ (size_t)C_DIM * C_DIM ];      // tf32-rounded proj_w
__device__ __nv_bfloat16  g_w1b [ (size_t)C_DIM * MLP_N ];
__device__ __nv_bfloat16  g_w2b [ (size_t)MLP_N * C_DIM ];

// ---------------- asm helpers --------------------------------------------------
#define CP_ASYNC16(dst_u32, src_ptr) \
    asm volatile("cp.async.cg.shared.global [%0], [%1], 16;\n" :: "r"(dst_u32), "l"(src_ptr))
#define CP_COMMIT() asm volatile("cp.async.commit_group;\n" ::)
#define CP_WAIT(n)  asm volatile("cp.async.wait_group %0;\n" :: "n"(n))

__device__ __forceinline__ uint32_t smem_u32(const void* p) {
    return (uint32_t)__cvta_generic_to_shared(p);
}

#define LDSM_X4(r0,r1,r2,r3,addr) \
    asm volatile("ldmatrix.sync.aligned.m8n8.x4.shared.b16 {%0,%1,%2,%3},[%4];\n" \
        : "=r"(r0),"=r"(r1),"=r"(r2),"=r"(r3) : "r"(addr))
#define LDSM_X4T(r0,r1,r2,r3,addr) \
    asm volatile("ldmatrix.sync.aligned.m8n8.x4.trans.shared.b16 {%0,%1,%2,%3},[%4];\n" \
        : "=r"(r0),"=r"(r1),"=r"(r2),"=r"(r3) : "r"(addr))

#define MMA_BF16(c, a, b) \
    asm volatile("mma.sync.aligned.m16n8k16.row.col.f32.bf16.bf16.f32 " \
        "{%0,%1,%2,%3},{%4,%5,%6,%7},{%8,%9},{%0,%1,%2,%3};\n" \
        : "+f"(c[0]),"+f"(c[1]),"+f"(c[2]),"+f"(c[3]) \
        : "r"(a[0]),"r"(a[1]),"r"(a[2]),"r"(a[3]),"r"(b[0]),"r"(b[1]))

#define MMA_TF32(c, a, b) \
    asm volatile("mma.sync.aligned.m16n8k8.row.col.f32.tf32.tf32.f32 " \
        "{%0,%1,%2,%3},{%4,%5,%6,%7},{%8,%9},{%0,%1,%2,%3};\n" \
        : "+f"(c[0]),"+f"(c[1]),"+f"(c[2]),"+f"(c[3]) \
        : "r"(a[0]),"r"(a[1]),"r"(a[2]),"r"(a[3]),"r"(b[0]),"r"(b[1]))

__device__ __forceinline__ float tf32r(float x) {
    uint32_t r;
    asm("cvt.rna.tf32.f32 %0, %1;\n" : "=r"(r) : "f"(x));
    return __uint_as_float(r);
}

// ---------------- l2 normalize along C=320, one warp per token ----------------
__global__ __launch_bounds__(256) void l2norm_kernel(const float* __restrict__ in,
                                                     float* __restrict__ out,
                                                     __nv_bfloat16* __restrict__ outb) {
    int row  = blockIdx.x * 8 + (threadIdx.x >> 5);
    int lane = threadIdx.x & 31;
    const float* p = in + (size_t)row * C_DIM;
    float v[10];
    float s = 0.f;
#pragma unroll
    for (int i = 0; i < 10; i++) { v[i] = p[lane + 32 * i]; s += v[i] * v[i]; }
#pragma unroll
    for (int sh = 16; sh; sh >>= 1) s += __shfl_xor_sync(0xffffffffu, s, sh);
    float n = fmaxf(sqrtf(s), 1e-12f);
    float inv = 1.0f / n;
    float* q = out + (size_t)row * C_DIM;
#pragma unroll
    for (int i = 0; i < 10; i++) {
        float o = v[i] * inv;
        q[lane + 32 * i] = o;
        outb[(size_t)row * C_DIM + lane + 32 * i] = __float2bfloat16(o);
    }
}

// ---------------- conversions --------------------------------------------------
__global__ __launch_bounds__(256) void cvt_bf16_kernel(const float* __restrict__ in,
                                                       __nv_bfloat16* __restrict__ out) {
    int i = (blockIdx.x * 256 + threadIdx.x) * 4;
    float4 v = *reinterpret_cast<const float4*>(in + i);
    __nv_bfloat162 lo = __float22bfloat162_rn(make_float2(v.x, v.y));
    __nv_bfloat162 hi = __float22bfloat162_rn(make_float2(v.z, v.w));
    uint32_t lou, hiu;
    memcpy(&lou, &lo, 4); memcpy(&hiu, &hi, 4);
    *reinterpret_cast<uint2*>(out + i) = make_uint2(lou, hiu);
}

__global__ __launch_bounds__(256) void cvt_tf32_kernel(const float* __restrict__ in,
                                                       float* __restrict__ out) {
    int i = (blockIdx.x * 256 + threadIdx.x) * 4;
    float4 v = *reinterpret_cast<const float4*>(in + i);
    v.x = tf32r(v.x); v.y = tf32r(v.y); v.z = tf32r(v.z); v.w = tf32r(v.w);
    *reinterpret_cast<float4*>(out + i) = v;
}

// ---------------- tf32 GEMM (pre-rounded inputs): 128x64x16, 8 warps ----------
// EPI 1: out = acc + bias + res    (proj -> xa)
template <int EPI>
__global__ __launch_bounds__(256) void gemm_tf32(
    const float* __restrict__ A, const float* __restrict__ Bw,
    const float* __restrict__ bias, const float* __restrict__ res,
    float* __restrict__ Cout, int M, int N, int K)
{
    __shared__ float As[2][128][20];
    __shared__ float Bs[2][16][72];

    const int tid = threadIdx.x, lane = tid & 31, wid = tid >> 5;
    const int wm = (wid >> 1) * 32, wn = (wid & 1) * 32;
    const int bm = blockIdx.y * 128, bn = blockIdx.x * 64;

    float acc[2][4][4];
#pragma unroll
    for (int i = 0; i < 2; i++)
#pragma unroll
        for (int j = 0; j < 4; j++)
#pragma unroll
            for (int r = 0; r < 4; r++) acc[i][j][r] = 0.f;

    const int ar = tid >> 2, ac = (tid & 3) * 4;
    const int br = tid >> 4, bc = (tid & 15) * 4;

    {
        CP_ASYNC16(smem_u32(&As[0][ar][ac]),       A + (size_t)(bm + ar) * K + ac);
        CP_ASYNC16(smem_u32(&As[0][ar + 64][ac]),  A + (size_t)(bm + ar + 64) * K + ac);
        CP_ASYNC16(smem_u32(&Bs[0][br][bc]),       Bw + (size_t)br * N + bn + bc);
        CP_COMMIT();
    }

    const int TT = K / 16;
    for (int t = 0; t < TT; t++) {
        int s = t & 1;
        if (t + 1 < TT) {
            int k0 = (t + 1) * 16;
            CP_ASYNC16(smem_u32(&As[s ^ 1][ar][ac]),      A + (size_t)(bm + ar) * K + k0 + ac);
            CP_ASYNC16(smem_u32(&As[s ^ 1][ar + 64][ac]), A + (size_t)(bm + ar + 64) * K + k0 + ac);
            CP_ASYNC16(smem_u32(&Bs[s ^ 1][br][bc]),      Bw + (size_t)(k0 + br) * N + bn + bc);
            CP_COMMIT();
            CP_WAIT(1);
        } else {
            CP_WAIT(0);
        }
        __syncthreads();

        const int g = lane >> 2, tg = lane & 3;
#pragma unroll
        for (int ks = 0; ks < 2; ks++) {
            uint32_t af[2][4], bf[4][2];
#pragma unroll
            for (int mt = 0; mt < 2; mt++) {
                int r0 = wm + mt * 16 + g;
                af[mt][0] = __float_as_uint(As[s][r0][ks * 8 + tg]);
                af[mt][1] = __float_as_uint(As[s][r0 + 8][ks * 8 + tg]);
                af[mt][2] = __float_as_uint(As[s][r0][ks * 8 + tg + 4]);
                af[mt][3] = __float_as_uint(As[s][r0 + 8][ks * 8 + tg + 4]);
            }
#pragma unroll
            for (int nt = 0; nt < 4; nt++) {
                int c0 = wn + nt * 8 + g;
                bf[nt][0] = __float_as_uint(Bs[s][ks * 8 + tg][c0]);
                bf[nt][1] = __float_as_uint(Bs[s][ks * 8 + tg + 4][c0]);
            }
#pragma unroll
            for (int mt = 0; mt < 2; mt++)
#pragma unroll
                for (int nt = 0; nt < 4; nt++)
                    MMA_TF32(acc[mt][nt], af[mt], bf[nt]);
        }
        __syncthreads();
    }

    const int g = lane >> 2, tg = lane & 3;
#pragma unroll
    for (int mt = 0; mt < 2; mt++) {
#pragma unroll
        for (int nt = 0; nt < 4; nt++) {
            int r0 = bm + wm + mt * 16 + g;
            int c0 = bn + wn + nt * 8 + tg * 2;
            float b0 = bias[c0], b1 = bias[c0 + 1];
#pragma unroll
            for (int half = 0; half < 2; half++) {
                int r = r0 + half * 8;
                float v0 = acc[mt][nt][half * 2 + 0] + b0;
                float v1 = acc[mt][nt][half * 2 + 1] + b1;
                if (EPI == 1) {
                    float2 rr = *reinterpret_cast<const float2*>(res + (size_t)r * N + c0);
                    v0 += rr.x; v1 += rr.y;
                }
                *reinterpret_cast<float2*>(Cout + (size_t)r * N + c0) = make_float2(v0, v1);
            }
        }
    }
}

// ---------------- bf16 GEMM: 128x64x32 block, 8 warps (4m x 2n) ---------------
// EPI 0: out(f32)  = acc + bias                        (qkv)
// EPI 2: out(bf16) = relu(acc)                         (mlp1 -> h)
// EPI 3: out(f32)  = res + relu(acc + bias) * gamma    (mlp2 -> final)
template <int EPI>
__global__ __launch_bounds__(256) void gemm_bf16(
    const __nv_bfloat16* __restrict__ A, const __nv_bfloat16* __restrict__ Bw,
    const float* __restrict__ bias, const float* __restrict__ res,
    const float* __restrict__ gamma, void* __restrict__ Cout,
    int M, int N, int K)
{
    __shared__ __nv_bfloat16 As[2][128][40];
    __shared__ __nv_bfloat16 Bs[2][32][72];

    const int tid = threadIdx.x, lane = tid & 31, wid = tid >> 5;
    const int wm = (wid >> 1) * 32, wn = (wid & 1) * 32;
    const int bm = blockIdx.y * 128, bn = blockIdx.x * 64;

    float acc[2][4][4];
#pragma unroll
    for (int i = 0; i < 2; i++)
#pragma unroll
        for (int j = 0; j < 4; j++)
#pragma unroll
            for (int r = 0; r < 4; r++) acc[i][j][r] = 0.f;

    const int ar = tid >> 2, ac = (tid & 3) * 8;
    const int br = tid >> 3, bc = (tid & 7) * 8;

    {
        CP_ASYNC16(smem_u32(&As[0][ar][ac]),      A + (size_t)(bm + ar) * K + ac);
        CP_ASYNC16(smem_u32(&As[0][ar + 64][ac]), A + (size_t)(bm + ar + 64) * K + ac);
        CP_ASYNC16(smem_u32(&Bs[0][br][bc]),      Bw + (size_t)br * N + bn + bc);
        CP_COMMIT();
    }

    const int TT = K / 32;
    for (int t = 0; t < TT; t++) {
        int s = t & 1;
        if (t + 1 < TT) {
            int k0 = (t + 1) * 32;
            CP_ASYNC16(smem_u32(&As[s ^ 1][ar][ac]),      A + (size_t)(bm + ar) * K + k0 + ac);
            CP_ASYNC16(smem_u32(&As[s ^ 1][ar + 64][ac]), A + (size_t)(bm + ar + 64) * K + k0 + ac);
            CP_ASYNC16(smem_u32(&Bs[s ^ 1][br][bc]),      Bw + (size_t)(k0 + br) * N + bn + bc);
            CP_COMMIT();
            CP_WAIT(1);
        } else {
            CP_WAIT(0);
        }
        __syncthreads();

#pragma unroll
        for (int ks = 0; ks < 2; ks++) {
            uint32_t af[2][4], bf[4][2];
#pragma unroll
            for (int mt = 0; mt < 2; mt++) {
                uint32_t addr = smem_u32(&As[s][wm + mt * 16 + (lane & 15)][ks * 16 + (lane >> 4) * 8]);
                LDSM_X4(af[mt][0], af[mt][1], af[mt][2], af[mt][3], addr);
            }
#pragma unroll
            for (int p = 0; p < 2; p++) {
                int row = ks * 16 + ((lane >> 3) & 1) * 8 + (lane & 7);
                int col = wn + p * 16 + (lane >> 4) * 8;
                uint32_t r0, r1, r2, r3;
                uint32_t addr = smem_u32(&Bs[s][row][col]);
                LDSM_X4T(r0, r1, r2, r3, addr);
                bf[p * 2][0] = r0; bf[p * 2][1] = r1;
                bf[p * 2 + 1][0] = r2; bf[p * 2 + 1][1] = r3;
            }
#pragma unroll
            for (int mt = 0; mt < 2; mt++)
#pragma unroll
                for (int nt = 0; nt < 4; nt++)
                    MMA_BF16(acc[mt][nt], af[mt], bf[nt]);
        }
        __syncthreads();
    }

    const int g = lane >> 2, tg = lane & 3;
#pragma unroll
    for (int mt = 0; mt < 2; mt++) {
#pragma unroll
        for (int nt = 0; nt < 4; nt++) {
            int r0 = bm + wm + mt * 16 + g;
            int c0 = bn + wn + nt * 8 + tg * 2;
#pragma unroll
            for (int half = 0; half < 2; half++) {
                int r = r0 + half * 8;
                float v0 = acc[mt][nt][half * 2 + 0];
                float v1 = acc[mt][nt][half * 2 + 1];
                if (EPI == 0) {
                    v0 += bias[c0]; v1 += bias[c0 + 1];
                    *reinterpret_cast<float2*>((float*)Cout + (size_t)r * N + c0) = make_float2(v0, v1);
                } else if (EPI == 2) {
                    v0 = fmaxf(v0, 0.f); v1 = fmaxf(v1, 0.f);
                    __nv_bfloat162 pk = __float22bfloat162_rn(make_float2(v0, v1));
                    uint32_t pku; memcpy(&pku, &pk, 4);
                    *reinterpret_cast<uint32_t*>((__nv_bfloat16*)Cout + (size_t)r * N + c0) = pku;
                } else { // EPI == 3
                    float2 rr = *reinterpret_cast<const float2*>(res + (size_t)r * N + c0);
                    float o0 = rr.x + fmaxf(v0 + bias[c0], 0.f) * gamma[c0];
                    float o1 = rr.y + fmaxf(v1 + bias[c0 + 1], 0.f) * gamma[c0 + 1];
                    *reinterpret_cast<float2*>((float*)Cout + (size_t)r * N + c0) = make_float2(o0, o1);
                }
            }
        }
    }
}

// ---------------- window attention, flash-style -------------------------------
// grid = (4 head-groups, 2048 windows), 256 threads, 8 warps.
// warp <-> head (hg*8+warp). Each lane owns 2 query rows fully in registers
// with online softmax; K/V staged in smem (broadcast reads). One sync total.
// Output rounded to tf32 at write (feeds tf32 proj GEMM).
__global__ __launch_bounds__(256) void attn_kernel(const float* __restrict__ qkv,
                                                   float* __restrict__ o) {
    const int w   = blockIdx.y;
    const int hg  = blockIdx.x;
    const int b   = w >> 8, rem = w & 255;
    const int wh  = rem >> 4, ww = rem & 15;
    const int tid = threadIdx.x, lane = tid & 31, warp = tid >> 5;
    const int head = hg * 8 + warp;

    __shared__ float ks[8][64][10];
    __shared__ float vs[8][64][10];

    const int base_tok = (b * 128 + wh * 8) * 128 + ww * 8;   // + i*128 + j

    // cooperative K/V load: 8 heads x 64 tokens x 20 channels
    for (int idx = tid; idx < 64 * 8 * 20; idx += 256) {
        int n  = idx / 160;
        int c  = idx - n * 160;
        int h2 = c / 20;
        int cc = c - h2 * 20;
        int tok = base_tok + (n >> 3) * 128 + (n & 7);
        float v = qkv[(size_t)tok * QKV_N + (hg * 8 + h2) * 30 + 10 + cc];
        if (cc < 10) ks[h2][n][cc] = v;
        else         vs[h2][n][cc - 10] = v;
    }
    __syncthreads();

    const float scale = 0.31622776601683794f;
    float q[2][10], acc[2][10];
    float mx[2] = {-1e30f, -1e30f}, l[2] = {0.f, 0.f};
    int toks[2];
#pragma unroll
    for (int p = 0; p < 2; p++) {
        int r = lane + p * 32;
        int tok = base_tok + (r >> 3) * 128 + (r & 7);
        toks[p] = tok;
        const float* qp = qkv + (size_t)tok * QKV_N + head * 30;
#pragma unroll
        for (int d = 0; d < 10; d++) { q[p][d] = qp[d]; acc[p][d] = 0.f; }
    }

    for (int m = 0; m < 64; m++) {
        float kv[10];
#pragma unroll
        for (int d = 0; d < 10; d++) kv[d] = ks[warp][m][d];
#pragma unroll
        for (int p = 0; p < 2; p++) {
            float s = 0.f;
#pragma unroll
            for (int d = 0; d < 10; d++) s += q[p][d] * kv[d];
            s *= scale;
            if (s > mx[p]) {
                float c = __expf(mx[p] - s);
                l[p] *= c;
#pragma unroll
                for (int d = 0; d < 10; d++) acc[p][d] *= c;
                mx[p] = s;
            }
            float e = __expf(s - mx[p]);
            l[p] += e;
#pragma unroll
            for (int d = 0; d < 10; d++) acc[p][d] += e * vs[warp][m][d];
        }
    }

#pragma unroll
    for (int p = 0; p < 2; p++) {
        float inv = 1.0f / l[p];
        float* op = o + (size_t)toks[p] * C_DIM + head * DHEAD;
#pragma unroll
        for (int d = 0; d < 10; d++) op[d] = tf32r(acc[p][d] * inv);
    }
}

// ---------------- launch ------------------------------------------------------
extern "C" void kernel_launch(void* const* d_in, const int* in_sizes, int n_in,
                              void* d_out, int out_size) {
    const float* x      = (const float*)d_in[0];
    const float* qkv_w  = (const float*)d_in[1];
    const float* qkv_b  = (const float*)d_in[2];
    const float* proj_w = (const float*)d_in[3];
    const float* proj_b = (const float*)d_in[4];
    const float* gamma  = (const float*)d_in[5];
    const float* w1     = (const float*)d_in[6];
    const float* w2     = (const float*)d_in[7];
    const float* b2     = (const float*)d_in[8];
    float* out = (float*)d_out;

    float *xn, *qkv, *ov, *xa, *pwt;
    __nv_bfloat16 *xnb, *hh, *qwb, *w1b, *w2b;
    cudaGetSymbolAddress((void**)&xn,  g_xn);
    cudaGetSymbolAddress((void**)&xnb, g_xnb);
    cudaGetSymbolAddress((void**)&qkv, g_qkv);
    cudaGetSymbolAddress((void**)&ov,  g_o);
    cudaGetSymbolAddress((void**)&xa,  g_xa);
    cudaGetSymbolAddress((void**)&pwt, g_pwt);
    cudaGetSymbolAddress((void**)&hh,  g_h);
    cudaGetSymbolAddress((void**)&qwb, g_qwb);
    cudaGetSymbolAddress((void**)&w1b, g_w1b);
    cudaGetSymbolAddress((void**)&w2b, g_w2b);

    const int M = T_TOKENS;
    dim3 blk(256);

    // weight conversions
    cvt_bf16_kernel<<<300, blk>>>(qkv_w, qwb);     // 320*960
    cvt_bf16_kernel<<<400, blk>>>(w1, w1b);        // 320*1280
    cvt_bf16_kernel<<<400, blk>>>(w2, w2b);        // 1280*320
    cvt_tf32_kernel<<<100, blk>>>(proj_w, pwt);    // 320*320

    // 1. xn,xnb = l2norm(x)
    l2norm_kernel<<<M / 8, blk>>>(x, xn, xnb);

    // 2. qkv = xnb @ qwb + qkv_b   (bf16 mma, fp32 out)
    gemm_bf16<0><<<dim3(QKV_N / 64, M / 128), blk>>>(xnb, qwb, qkv_b, nullptr, nullptr, qkv, M, QKV_N, C_DIM);

    // 3. windowed attention -> ov (tf32-rounded)
    attn_kernel<<<dim3(4, 2048), blk>>>(qkv, ov);

    // 4. xa = xn + ov @ pwt + proj_b   (tf32, pre-rounded inputs)
    gemm_tf32<1><<<dim3(C_DIM / 64, M / 128), blk>>>(ov, pwt, proj_b, xn, xa, M, C_DIM, C_DIM);

    // 5. xn,xnb = l2norm(xa)
    l2norm_kernel<<<M / 8, blk>>>(xa, xn, xnb);

    // 6. h = relu(xnb @ w1b)   (bf16 out)
    gemm_bf16<2><<<dim3(MLP_N / 64, M / 128), blk>>>(xnb, w1b, nullptr, nullptr, nullptr, hh, M, MLP_N, C_DIM);

    // 7. out = xn + relu(h @ w2b + b2) * gamma
    gemm_bf16<3><<<dim3(C_DIM / 64, M / 128), blk>>>(hh, w2b, b2, xn, gamma, out, M, C_DIM, MLP_N);
}

// round 10
// speedup vs baseline: 3.6134x; 1.0639x over previous
#include <cuda_runtime.h>
#include <cuda_bf16.h>
#include <cstdint>
#include <cstddef>

// Problem constants
#define T_TOKENS 131072      // 8*128*128
#define C_DIM    320
#define QKV_N    960
#define MLP_N    1280
#define HEADS    32
#define DHEAD    10

// ---------------- scratch (device globals) ------------------------------------
__device__ float          g_xn  [ (size_t)T_TOKENS * C_DIM ];
__device__ __nv_bfloat16  g_xnb [ (size_t)T_TOKENS * C_DIM ];
__device__ float          g_qkv [ (size_t)T_TOKENS * QKV_N ];
__device__ __nv_bfloat16  g_ovb [ (size_t)T_TOKENS * C_DIM ];   // attn out, bf16
__device__ float          g_xa  [ (size_t)T_TOKENS * C_DIM ];
__device__ __nv_bfloat16  g_h   [ (size_t)T_TOKENS * MLP_N ];
__device__ __nv_bfloat16  g_qwb [ (size_t)C_DIM * QKV_N ];
__device__ __nv_bfloat16  g_pwb [ (size_t)C_DIM * C_DIM ];
__device__ __nv_bfloat16  g_w1b [ (size_t)C_DIM * MLP_N ];
__device__ __nv_bfloat16  g_w2b [ (size_t)MLP_N * C_DIM ];

// ---------------- asm helpers --------------------------------------------------
#define CP_ASYNC16(dst_u32, src_ptr) \
    asm volatile("cp.async.cg.shared.global [%0], [%1], 16;\n" :: "r"(dst_u32), "l"(src_ptr))
#define CP_COMMIT() asm volatile("cp.async.commit_group;\n" ::)
#define CP_WAIT(n)  asm volatile("cp.async.wait_group %0;\n" :: "n"(n))

__device__ __forceinline__ uint32_t smem_u32(const void* p) {
    return (uint32_t)__cvta_generic_to_shared(p);
}

#define LDSM_X4(r0,r1,r2,r3,addr) \
    asm volatile("ldmatrix.sync.aligned.m8n8.x4.shared.b16 {%0,%1,%2,%3},[%4];\n" \
        : "=r"(r0),"=r"(r1),"=r"(r2),"=r"(r3) : "r"(addr))
#define LDSM_X4T(r0,r1,r2,r3,addr) \
    asm volatile("ldmatrix.sync.aligned.m8n8.x4.trans.shared.b16 {%0,%1,%2,%3},[%4];\n" \
        : "=r"(r0),"=r"(r1),"=r"(r2),"=r"(r3) : "r"(addr))

#define MMA_BF16(c, a, b) \
    asm volatile("mma.sync.aligned.m16n8k16.row.col.f32.bf16.bf16.f32 " \
        "{%0,%1,%2,%3},{%4,%5,%6,%7},{%8,%9},{%0,%1,%2,%3};\n" \
        : "+f"(c[0]),"+f"(c[1]),"+f"(c[2]),"+f"(c[3]) \
        : "r"(a[0]),"r"(a[1]),"r"(a[2]),"r"(a[3]),"r"(b[0]),"r"(b[1]))

// ---------------- l2 normalize along C=320, one warp per token ----------------
__global__ __launch_bounds__(256) void l2norm_kernel(const float* __restrict__ in,
                                                     float* __restrict__ out,
                                                     __nv_bfloat16* __restrict__ outb) {
    int row  = blockIdx.x * 8 + (threadIdx.x >> 5);
    int lane = threadIdx.x & 31;
    const float* p = in + (size_t)row * C_DIM;
    float v[10];
    float s = 0.f;
#pragma unroll
    for (int i = 0; i < 10; i++) { v[i] = p[lane + 32 * i]; s += v[i] * v[i]; }
#pragma unroll
    for (int sh = 16; sh; sh >>= 1) s += __shfl_xor_sync(0xffffffffu, s, sh);
    float n = fmaxf(sqrtf(s), 1e-12f);
    float inv = 1.0f / n;
    float* q = out + (size_t)row * C_DIM;
#pragma unroll
    for (int i = 0; i < 10; i++) {
        float o = v[i] * inv;
        q[lane + 32 * i] = o;
        outb[(size_t)row * C_DIM + lane + 32 * i] = __float2bfloat16(o);
    }
}

// ---------------- fp32 -> bf16 conversion (weights) ---------------------------
__global__ __launch_bounds__(256) void cvt_bf16_kernel(const float* __restrict__ in,
                                                       __nv_bfloat16* __restrict__ out) {
    int i = (blockIdx.x * 256 + threadIdx.x) * 4;
    float4 v = *reinterpret_cast<const float4*>(in + i);
    __nv_bfloat162 lo = __float22bfloat162_rn(make_float2(v.x, v.y));
    __nv_bfloat162 hi = __float22bfloat162_rn(make_float2(v.z, v.w));
    uint32_t lou, hiu;
    memcpy(&lou, &lo, 4); memcpy(&hiu, &hi, 4);
    *reinterpret_cast<uint2*>(out + i) = make_uint2(lou, hiu);
}

// ---------------- bf16 GEMM: 128x64x32 tile, 3-stage cp.async, 8 warps --------
// EPI 0: out(f32)  = acc + bias                        (qkv)
// EPI 1: out(f32)  = acc + bias + res                  (proj -> xa)
// EPI 2: out(bf16) = relu(acc)                         (mlp1 -> h)
// EPI 3: out(f32)  = res + relu(acc + bias) * gamma    (mlp2 -> final)
template <int EPI>
__global__ __launch_bounds__(256) void gemm_bf16(
    const __nv_bfloat16* __restrict__ A, const __nv_bfloat16* __restrict__ Bw,
    const float* __restrict__ bias, const float* __restrict__ res,
    const float* __restrict__ gamma, void* __restrict__ Cout,
    int M, int N, int K)
{
    __shared__ __nv_bfloat16 As[3][128][40];   // 128 x 32, pad->40
    __shared__ __nv_bfloat16 Bs[3][32][72];    //  32 x 64, pad->72

    const int tid = threadIdx.x, lane = tid & 31, wid = tid >> 5;
    const int wm = (wid >> 1) * 32, wn = (wid & 1) * 32;
    const int bm = blockIdx.y * 128, bn = blockIdx.x * 64;

    float acc[2][4][4];
#pragma unroll
    for (int i = 0; i < 2; i++)
#pragma unroll
        for (int j = 0; j < 4; j++)
#pragma unroll
            for (int r = 0; r < 4; r++) acc[i][j][r] = 0.f;

    const int ar = tid >> 2, ac = (tid & 3) * 8;   // A: 2x 16B chunks per thread
    const int br = tid >> 3, bc = (tid & 7) * 8;   // B: 1x 16B chunk per thread

    // prologue: stages 0,1 (K >= 64 for all our shapes)
#pragma unroll
    for (int p = 0; p < 2; p++) {
        int k0 = p * 32;
        CP_ASYNC16(smem_u32(&As[p][ar][ac]),      A + (size_t)(bm + ar) * K + k0 + ac);
        CP_ASYNC16(smem_u32(&As[p][ar + 64][ac]), A + (size_t)(bm + ar + 64) * K + k0 + ac);
        CP_ASYNC16(smem_u32(&Bs[p][br][bc]),      Bw + (size_t)(k0 + br) * N + bn + bc);
        CP_COMMIT();
    }

    const int TT = K / 32;
    int s = 0;
    for (int t = 0; t < TT; t++) {
        CP_WAIT(1);               // tile t's group complete
        __syncthreads();

        // issue loads for tile t+2 (stage buffer freed by this barrier)
        if (t + 2 < TT) {
            int st = s + 2 >= 3 ? s - 1 : s + 2;
            int k0 = (t + 2) * 32;
            CP_ASYNC16(smem_u32(&As[st][ar][ac]),      A + (size_t)(bm + ar) * K + k0 + ac);
            CP_ASYNC16(smem_u32(&As[st][ar + 64][ac]), A + (size_t)(bm + ar + 64) * K + k0 + ac);
            CP_ASYNC16(smem_u32(&Bs[st][br][bc]),      Bw + (size_t)(k0 + br) * N + bn + bc);
            CP_COMMIT();
        } else {
            CP_COMMIT();          // empty group keeps wait accounting uniform
        }

#pragma unroll
        for (int ks = 0; ks < 2; ks++) {
            uint32_t af[2][4], bf[4][2];
#pragma unroll
            for (int mt = 0; mt < 2; mt++) {
                uint32_t addr = smem_u32(&As[s][wm + mt * 16 + (lane & 15)][ks * 16 + (lane >> 4) * 8]);
                LDSM_X4(af[mt][0], af[mt][1], af[mt][2], af[mt][3], addr);
            }
#pragma unroll
            for (int p = 0; p < 2; p++) {
                int row = ks * 16 + ((lane >> 3) & 1) * 8 + (lane & 7);
                int col = wn + p * 16 + (lane >> 4) * 8;
                uint32_t r0, r1, r2, r3;
                uint32_t addr = smem_u32(&Bs[s][row][col]);
                LDSM_X4T(r0, r1, r2, r3, addr);
                bf[p * 2][0] = r0; bf[p * 2][1] = r1;
                bf[p * 2 + 1][0] = r2; bf[p * 2 + 1][1] = r3;
            }
#pragma unroll
            for (int mt = 0; mt < 2; mt++)
#pragma unroll
                for (int nt = 0; nt < 4; nt++)
                    MMA_BF16(acc[mt][nt], af[mt], bf[nt]);
        }
        s = (s + 1 == 3) ? 0 : s + 1;
    }

    // epilogue
    const int g = lane >> 2, tg = lane & 3;
#pragma unroll
    for (int mt = 0; mt < 2; mt++) {
#pragma unroll
        for (int nt = 0; nt < 4; nt++) {
            int r0 = bm + wm + mt * 16 + g;
            int c0 = bn + wn + nt * 8 + tg * 2;
#pragma unroll
            for (int half = 0; half < 2; half++) {
                int r = r0 + half * 8;
                float v0 = acc[mt][nt][half * 2 + 0];
                float v1 = acc[mt][nt][half * 2 + 1];
                if (EPI == 0) {
                    v0 += bias[c0]; v1 += bias[c0 + 1];
                    *reinterpret_cast<float2*>((float*)Cout + (size_t)r * N + c0) = make_float2(v0, v1);
                } else if (EPI == 1) {
                    float2 rr = *reinterpret_cast<const float2*>(res + (size_t)r * N + c0);
                    v0 += bias[c0] + rr.x; v1 += bias[c0 + 1] + rr.y;
                    *reinterpret_cast<float2*>((float*)Cout + (size_t)r * N + c0) = make_float2(v0, v1);
                } else if (EPI == 2) {
                    v0 = fmaxf(v0, 0.f); v1 = fmaxf(v1, 0.f);
                    __nv_bfloat162 pk = __float22bfloat162_rn(make_float2(v0, v1));
                    uint32_t pku; memcpy(&pku, &pk, 4);
                    *reinterpret_cast<uint32_t*>((__nv_bfloat16*)Cout + (size_t)r * N + c0) = pku;
                } else { // EPI == 3
                    float2 rr = *reinterpret_cast<const float2*>(res + (size_t)r * N + c0);
                    float o0 = rr.x + fmaxf(v0 + bias[c0], 0.f) * gamma[c0];
                    float o1 = rr.y + fmaxf(v1 + bias[c0 + 1], 0.f) * gamma[c0 + 1];
                    *reinterpret_cast<float2*>((float*)Cout + (size_t)r * N + c0) = make_float2(o0, o1);
                }
            }
        }
    }
}

// ---------------- window attention, flash-style, bf16 out ---------------------
// grid = (4 head-groups, 2048 windows), 256 threads, 8 warps, head = hg*8+warp.
// Each lane owns 2 query rows in registers with online softmax; one sync total.
__global__ __launch_bounds__(256) void attn_kernel(const float* __restrict__ qkv,
                                                   __nv_bfloat16* __restrict__ o) {
    const int w   = blockIdx.y;
    const int hg  = blockIdx.x;
    const int b   = w >> 8, rem = w & 255;
    const int wh  = rem >> 4, ww = rem & 15;
    const int tid = threadIdx.x, lane = tid & 31, warp = tid >> 5;
    const int head = hg * 8 + warp;

    __shared__ float ks[8][64][10];
    __shared__ float vs[8][64][10];

    const int base_tok = (b * 128 + wh * 8) * 128 + ww * 8;

    for (int idx = tid; idx < 64 * 8 * 20; idx += 256) {
        int n  = idx / 160;
        int c  = idx - n * 160;
        int h2 = c / 20;
        int cc = c - h2 * 20;
        int tok = base_tok + (n >> 3) * 128 + (n & 7);
        float v = qkv[(size_t)tok * QKV_N + (hg * 8 + h2) * 30 + 10 + cc];
        if (cc < 10) ks[h2][n][cc] = v;
        else         vs[h2][n][cc - 10] = v;
    }
    __syncthreads();

    const float scale = 0.31622776601683794f;
    float q[2][10], acc[2][10];
    float mx[2] = {-1e30f, -1e30f}, l[2] = {0.f, 0.f};
    int toks[2];
#pragma unroll
    for (int p = 0; p < 2; p++) {
        int r = lane + p * 32;
        int tok = base_tok + (r >> 3) * 128 + (r & 7);
        toks[p] = tok;
        const float* qp = qkv + (size_t)tok * QKV_N + head * 30;
#pragma unroll
        for (int d = 0; d < 10; d++) { q[p][d] = qp[d]; acc[p][d] = 0.f; }
    }

    for (int m = 0; m < 64; m++) {
        float kv[10];
#pragma unroll
        for (int d = 0; d < 10; d++) kv[d] = ks[warp][m][d];
#pragma unroll
        for (int p = 0; p < 2; p++) {
            float s = 0.f;
#pragma unroll
            for (int d = 0; d < 10; d++) s += q[p][d] * kv[d];
            s *= scale;
            if (s > mx[p]) {
                float c = __expf(mx[p] - s);
                l[p] *= c;
#pragma unroll
                for (int d = 0; d < 10; d++) acc[p][d] *= c;
                mx[p] = s;
            }
            float e = __expf(s - mx[p]);
            l[p] += e;
#pragma unroll
            for (int d = 0; d < 10; d++) acc[p][d] += e * vs[warp][m][d];
        }
    }

#pragma unroll
    for (int p = 0; p < 2; p++) {
        float inv = 1.0f / l[p];
        uint32_t* op = reinterpret_cast<uint32_t*>(o + (size_t)toks[p] * C_DIM + head * DHEAD);
#pragma unroll
        for (int d = 0; d < 5; d++) {
            __nv_bfloat162 pk = __float22bfloat162_rn(
                make_float2(acc[p][2 * d] * inv, acc[p][2 * d + 1] * inv));
            uint32_t pku; memcpy(&pku, &pk, 4);
            op[d] = pku;
        }
    }
}

// ---------------- launch ------------------------------------------------------
extern "C" void kernel_launch(void* const* d_in, const int* in_sizes, int n_in,
                              void* d_out, int out_size) {
    const float* x      = (const float*)d_in[0];
    const float* qkv_w  = (const float*)d_in[1];
    const float* qkv_b  = (const float*)d_in[2];
    const float* proj_w = (const float*)d_in[3];
    const float* proj_b = (const float*)d_in[4];
    const float* gamma  = (const float*)d_in[5];
    const float* w1     = (const float*)d_in[6];
    const float* w2     = (const float*)d_in[7];
    const float* b2     = (const float*)d_in[8];
    float* out = (float*)d_out;

    float *xn, *qkv, *xa;
    __nv_bfloat16 *xnb, *ovb, *hh, *qwb, *pwb, *w1b, *w2b;
    cudaGetSymbolAddress((void**)&xn,  g_xn);
    cudaGetSymbolAddress((void**)&xnb, g_xnb);
    cudaGetSymbolAddress((void**)&qkv, g_qkv);
    cudaGetSymbolAddress((void**)&ovb, g_ovb);
    cudaGetSymbolAddress((void**)&xa,  g_xa);
    cudaGetSymbolAddress((void**)&hh,  g_h);
    cudaGetSymbolAddress((void**)&qwb, g_qwb);
    cudaGetSymbolAddress((void**)&pwb, g_pwb);
    cudaGetSymbolAddress((void**)&w1b, g_w1b);
    cudaGetSymbolAddress((void**)&w2b, g_w2b);

    const int M = T_TOKENS;
    dim3 blk(256);

    // weight conversions (fp32 -> bf16)
    cvt_bf16_kernel<<<300, blk>>>(qkv_w, qwb);     // 320*960
    cvt_bf16_kernel<<<100, blk>>>(proj_w, pwb);    // 320*320
    cvt_bf16_kernel<<<400, blk>>>(w1, w1b);        // 320*1280
    cvt_bf16_kernel<<<400, blk>>>(w2, w2b);        // 1280*320

    // 1. xn,xnb = l2norm(x)
    l2norm_kernel<<<M / 8, blk>>>(x, xn, xnb);

    // 2. qkv = xnb @ qwb + qkv_b  (f32 out)
    gemm_bf16<0><<<dim3(QKV_N / 64, M / 128), blk>>>(xnb, qwb, qkv_b, nullptr, nullptr, qkv, M, QKV_N, C_DIM);

    // 3. windowed attention -> ovb (bf16)
    attn_kernel<<<dim3(4, 2048), blk>>>(qkv, ovb);

    // 4. xa = xn + ovb @ pwb + proj_b
    gemm_bf16<1><<<dim3(C_DIM / 64, M / 128), blk>>>(ovb, pwb, proj_b, xn, nullptr, xa, M, C_DIM, C_DIM);

    // 5. xn,xnb = l2norm(xa)
    l2norm_kernel<<<M / 8, blk>>>(xa, xn, xnb);

    // 6. h = relu(xnb @ w1b)   (bf16 out)
    gemm_bf16<2><<<dim3(MLP_N / 64, M / 128), blk>>>(xnb, w1b, nullptr, nullptr, nullptr, hh, M, MLP_N, C_DIM);

    // 7. out = xn + relu(h @ w2b + b2) * gamma
    gemm_bf16<3><<<dim3(C_DIM / 64, M / 128), blk>>>(hh, w2b, b2, xn, gamma, out, M, C_DIM, MLP_N);
}